// round 9
// baseline (speedup 1.0000x reference)
#include <cuda_runtime.h>
#include <cuda_fp16.h>

#define NN 100000
#define NE 1600000
#define NG 256
#define SCAN_NB ((NN + 255) / 256)   // 391

// Scratch (static __device__ arrays; no allocation anywhere)
__device__ float  g_bufA[NN * 16];   // L0 output (fp32)
__device__ float  g_bufB[NN * 32];   // L1 output (fp32)
__device__ __half g_t16[NN * 16];    // L0 scatter operand (fp16); later reused for t3 (half2/node)
__device__ __half g_h16[NN * 16];    // fp16 copy of L0 output (L1 gather operand)
__device__ __half g_h16b[NN * 32];   // fp16 copy of L1 output (L2 gather operand)
__device__ float  g_rbuf[NN * 16];   // r0 = x@Wr0+b0 (fp32); later reused for r3 (float2/node)
__device__ int    g_deg[NN];
__device__ int    g_pos[NN];
__device__ int    g_off[NN + 1];
__device__ int    g_bsum[SCAN_NB];
__device__ int    g_csr[NE];
__device__ float  g_pool[NG * 2];
__device__ float  g_gcnt[NG];
__device__ int    g_done;            // zero-init; self-resetting

// ---------------- CSR build ----------------

__global__ void k_zero_misc() {
    int i = blockIdx.x * blockDim.x + threadIdx.x;
    if (i < NN) { g_deg[i] = 0; g_pos[i] = 0; }
    if (i < NG * 2) g_pool[i] = 0.f;
    if (i < NG) g_gcnt[i] = 0.f;
}

__global__ void k_deg(const int* __restrict__ dst) {
    int e = blockIdx.x * blockDim.x + threadIdx.x;
    if (e < NE) atomicAdd(&g_deg[dst[e]], 1);
}

__global__ void k_scan1() {
    __shared__ int sh[256];
    int t = threadIdx.x;
    int i = blockIdx.x * 256 + t;
    sh[t] = (i < NN) ? g_deg[i] : 0;
    __syncthreads();
    for (int o = 128; o > 0; o >>= 1) {
        if (t < o) sh[t] += sh[t + o];
        __syncthreads();
    }
    if (t == 0) g_bsum[blockIdx.x] = sh[0];
}

// fused: block offset (sum of prior block sums) + inner exclusive scan
__global__ void k_scan23() {
    __shared__ int sh[256];
    __shared__ int sred[256];
    int t = threadIdx.x;
    int bid = blockIdx.x;
    // block offset = sum_{j < bid} g_bsum[j]
    int partial = 0;
    for (int j = t; j < SCAN_NB; j += 256)
        if (j < bid) partial += g_bsum[j];
    sred[t] = partial;
    __syncthreads();
    for (int o = 128; o > 0; o >>= 1) {
        if (t < o) sred[t] += sred[t + o];
        __syncthreads();
    }
    int boff = sred[0];
    // inner inclusive scan of this block's degrees
    int i = bid * 256 + t;
    int v = (i < NN) ? g_deg[i] : 0;
    sh[t] = v;
    __syncthreads();
    for (int o = 1; o < 256; o <<= 1) {
        int u = (t >= o) ? sh[t - o] : 0;
        __syncthreads();
        sh[t] += u;
        __syncthreads();
    }
    if (i < NN) g_off[i] = boff + sh[t] - v;
    if (i == NN - 1) g_off[NN] = NE;
}

__global__ void k_fill(const int* __restrict__ src, const int* __restrict__ dst) {
    int e = blockIdx.x * blockDim.x + threadIdx.x;
    if (e >= NE) return;
    int d = dst[e];
    int p = g_off[d] + atomicAdd(&g_pos[d], 1);
    g_csr[p] = src[e];
}

// ---------------- helpers ----------------

__device__ __forceinline__ void acc8_u4(float* a, uint4 v) {
    float2 p;
    p = __half22float2(*reinterpret_cast<__half2*>(&v.x)); a[0] += p.x; a[1] += p.y;
    p = __half22float2(*reinterpret_cast<__half2*>(&v.y)); a[2] += p.x; a[3] += p.y;
    p = __half22float2(*reinterpret_cast<__half2*>(&v.z)); a[4] += p.x; a[5] += p.y;
    p = __half22float2(*reinterpret_cast<__half2*>(&v.w)); a[6] += p.x; a[7] += p.y;
}

// ---------------- L0 prep: t0 = x@Wl0 (fp16), r0 = x@Wr0 + b0 (fp32) ----------------

__global__ void k_prep0(const float* __restrict__ x,
                        const float* __restrict__ Wl,
                        const float* __restrict__ bl,
                        const float* __restrict__ Wr) {
    __shared__ float sWl[56 * 16];
    __shared__ float sWr[56 * 16];
    __shared__ float sb[16];
    for (int idx = threadIdx.x; idx < 56 * 16; idx += blockDim.x) {
        sWl[idx] = Wl[idx];
        sWr[idx] = Wr[idx];
    }
    if (threadIdx.x < 16) sb[threadIdx.x] = bl[threadIdx.x];
    __syncthreads();
    int i = blockIdx.x * blockDim.x + threadIdx.x;
    if (i >= NN) return;
    float al[16], ar[16];
#pragma unroll
    for (int j = 0; j < 16; j++) { al[j] = 0.f; ar[j] = sb[j]; }
#pragma unroll 2
    for (int k = 0; k < 56; k++) {
        float hv = x[(size_t)i * 56 + k];
#pragma unroll
        for (int j = 0; j < 16; j++) {
            al[j] += hv * sWl[k * 16 + j];
            ar[j] += hv * sWr[k * 16 + j];
        }
    }
    // t0 row: 16 halves = 2 x uint4
    uint4 u[2];
    __half2* hp = reinterpret_cast<__half2*>(u);
#pragma unroll
    for (int j = 0; j < 8; j++) hp[j] = __floats2half2_rn(al[2 * j], al[2 * j + 1]);
    uint4* t0v = reinterpret_cast<uint4*>(g_t16);
    t0v[(size_t)i * 2 + 0] = u[0];
    t0v[(size_t)i * 2 + 1] = u[1];
#pragma unroll
    for (int j = 0; j < 16; j++) g_rbuf[(size_t)i * 16 + j] = ar[j];
}

// ---------------- L0 gather (pre): bufA = relu(agg/deg + r0), + fp16 copy g_h16 ----------------
// lane = (slot:4 | c8:1), 16 edge slots, each lane loads half a row (uint4 = 8 halves)

__global__ void k_g16pre() {
    int gw = (blockIdx.x * blockDim.x + threadIdx.x) >> 5;
    if (gw >= NN) return;
    int lane = threadIdx.x & 31;
    int c8 = lane & 1;
    int slot = lane >> 1;
    int s0 = g_off[gw];
    int deg = g_off[gw + 1] - s0;
    const uint4* tv = reinterpret_cast<const uint4*>(g_t16);
    float acc[8];
#pragma unroll
    for (int j = 0; j < 8; j++) acc[j] = 0.f;
    for (int base = 0; base < deg; base += 32) {
        int idx = base + lane;
        int si = (idx < deg) ? g_csr[s0 + idx] : 0;
        int lim = deg - base;
#pragma unroll
        for (int jb = 0; jb < 32; jb += 16) {
            int j = jb + slot;
            int s = __shfl_sync(0xffffffffu, si, j);
            if (j < lim) acc8_u4(acc, tv[(size_t)s * 2 + c8]);
        }
    }
#pragma unroll
    for (int m = 2; m < 32; m <<= 1) {
#pragma unroll
        for (int j = 0; j < 8; j++) acc[j] += __shfl_xor_sync(0xffffffffu, acc[j], m);
    }
    // lanes 0 (c8=0: ch 0-7) and 1 (c8=1: ch 8-15)
    if (lane < 2) {
        float inv = 1.f / fmaxf((float)deg, 1.f);
        float o[8];
#pragma unroll
        for (int j = 0; j < 8; j++) {
            float rv = g_rbuf[(size_t)gw * 16 + c8 * 8 + j];
            o[j] = fmaxf(acc[j] * inv + rv, 0.f);
        }
        float4* outv = reinterpret_cast<float4*>(g_bufA + (size_t)gw * 16 + c8 * 8);
        outv[0] = make_float4(o[0], o[1], o[2], o[3]);
        outv[1] = make_float4(o[4], o[5], o[6], o[7]);
        uint4 u;
        __half2* hp = reinterpret_cast<__half2*>(&u);
#pragma unroll
        for (int j = 0; j < 4; j++) hp[j] = __floats2half2_rn(o[2 * j], o[2 * j + 1]);
        reinterpret_cast<uint4*>(g_h16)[(size_t)gw * 2 + c8] = u;
    }
}

// ---------------- L1 gather (post, 16->32): bufB = relu((agg/deg)@Wl1 + b1 + h@Wr1), + fp16 copy ----------------

__global__ void __launch_bounds__(256) k_g16post(const float* __restrict__ Wl,
                                                 const float* __restrict__ bl,
                                                 const float* __restrict__ Wr) {
    __shared__ float sWl[16 * 32];
    __shared__ float sWr[16 * 32];
    __shared__ float sb[32];
    for (int idx = threadIdx.x; idx < 16 * 32; idx += blockDim.x) {
        sWl[idx] = Wl[idx];
        sWr[idx] = Wr[idx];
    }
    if (threadIdx.x < 32) sb[threadIdx.x] = bl[threadIdx.x];
    __syncthreads();
    int gw = (blockIdx.x * blockDim.x + threadIdx.x) >> 5;
    if (gw >= NN) return;
    int lane = threadIdx.x & 31;
    int c8 = lane & 1;
    int slot = lane >> 1;
    int s0 = g_off[gw];
    int deg = g_off[gw + 1] - s0;
    const uint4* tv = reinterpret_cast<const uint4*>(g_h16);
    float acc[8];
#pragma unroll
    for (int j = 0; j < 8; j++) acc[j] = 0.f;
    for (int base = 0; base < deg; base += 32) {
        int idx = base + lane;
        int si = (idx < deg) ? g_csr[s0 + idx] : 0;
        int lim = deg - base;
#pragma unroll
        for (int jb = 0; jb < 32; jb += 16) {
            int j = jb + slot;
            int s = __shfl_sync(0xffffffffu, si, j);
            if (j < lim) acc8_u4(acc, tv[(size_t)s * 2 + c8]);
        }
    }
#pragma unroll
    for (int m = 2; m < 32; m <<= 1) {
#pragma unroll
        for (int j = 0; j < 8; j++) acc[j] += __shfl_xor_sync(0xffffffffu, acc[j], m);
    }
    // lane0: ch 0-7, lane1: ch 8-15
    float inv = 1.f / fmaxf((float)deg, 1.f);
    float hv_mine = (lane < 16) ? g_bufA[(size_t)gw * 16 + lane] : 0.f;
    float o = sb[lane];
#pragma unroll
    for (int k = 0; k < 16; k++) {
        float aggk = __shfl_sync(0xffffffffu, acc[k & 7], k >> 3) * inv;
        float hk = __shfl_sync(0xffffffffu, hv_mine, k);
        o += aggk * sWl[k * 32 + lane] + hk * sWr[k * 32 + lane];
    }
    o = fmaxf(o, 0.f);
    g_bufB[(size_t)gw * 32 + lane] = o;
    g_h16b[(size_t)gw * 32 + lane] = __float2half(o);
}

// ---------------- L2 gather (post, 32->64) + fused L3 prep ----------------
// out row h3 (64-wide) lives in regs (o0,o1 per lane); directly emits
// t3 = h3@Wl3 (half2) and r3 = h3@Wr3 + b3 (float2).

__global__ void __launch_bounds__(256) k_g32post(const float* __restrict__ Wl,
                                                 const float* __restrict__ bl,
                                                 const float* __restrict__ Wr,
                                                 const float* __restrict__ Wl3,
                                                 const float* __restrict__ bl3,
                                                 const float* __restrict__ Wr3) {
    __shared__ float sWl[32 * 64];
    __shared__ float sWr[32 * 64];
    __shared__ float sb[64];
    __shared__ float sWl3[64 * 2];
    __shared__ float sWr3[64 * 2];
    __shared__ float sb3[2];
    for (int idx = threadIdx.x; idx < 32 * 64; idx += blockDim.x) {
        sWl[idx] = Wl[idx];
        sWr[idx] = Wr[idx];
    }
    if (threadIdx.x < 64) sb[threadIdx.x] = bl[threadIdx.x];
    if (threadIdx.x < 128) { sWl3[threadIdx.x] = Wl3[threadIdx.x]; sWr3[threadIdx.x] = Wr3[threadIdx.x]; }
    if (threadIdx.x < 2) sb3[threadIdx.x] = bl3[threadIdx.x];
    __syncthreads();
    int gw = (blockIdx.x * blockDim.x + threadIdx.x) >> 5;
    if (gw >= NN) return;
    int lane = threadIdx.x & 31;
    int c4 = lane & 3;    // quarter-row (8 halves)
    int slot = lane >> 2; // 8 edge slots
    int s0 = g_off[gw];
    int deg = g_off[gw + 1] - s0;
    const uint4* tv = reinterpret_cast<const uint4*>(g_h16b);
    float acc[8];
#pragma unroll
    for (int j = 0; j < 8; j++) acc[j] = 0.f;
    for (int base = 0; base < deg; base += 32) {
        int idx = base + lane;
        int si = (idx < deg) ? g_csr[s0 + idx] : 0;
        int lim = deg - base;
#pragma unroll
        for (int jb = 0; jb < 32; jb += 8) {
            int j = jb + slot;
            int s = __shfl_sync(0xffffffffu, si, j);
            if (j < lim) acc8_u4(acc, tv[(size_t)s * 4 + c4]);
        }
    }
#pragma unroll
    for (int m = 4; m < 32; m <<= 1) {
#pragma unroll
        for (int j = 0; j < 8; j++) acc[j] += __shfl_xor_sync(0xffffffffu, acc[j], m);
    }
    // lanes 0..3: lane c holds channels c*8..c*8+7
    float inv = 1.f / fmaxf((float)deg, 1.f);
    float hv_mine = g_bufB[(size_t)gw * 32 + lane];
    float o0 = sb[lane], o1 = sb[lane + 32];
#pragma unroll
    for (int k = 0; k < 32; k++) {
        float aggk = __shfl_sync(0xffffffffu, acc[k & 7], k >> 3) * inv;
        float hk = __shfl_sync(0xffffffffu, hv_mine, k);
        o0 += aggk * sWl[k * 64 + lane] + hk * sWr[k * 64 + lane];
        o1 += aggk * sWl[k * 64 + lane + 32] + hk * sWr[k * 64 + lane + 32];
    }
    o0 = fmaxf(o0, 0.f);
    o1 = fmaxf(o1, 0.f);
    // fused L3 prep: lane owns h3[lane] = o0 and h3[lane+32] = o1
    float t3p0 = o0 * sWl3[lane * 2 + 0] + o1 * sWl3[(lane + 32) * 2 + 0];
    float t3p1 = o0 * sWl3[lane * 2 + 1] + o1 * sWl3[(lane + 32) * 2 + 1];
    float r3p0 = o0 * sWr3[lane * 2 + 0] + o1 * sWr3[(lane + 32) * 2 + 0];
    float r3p1 = o0 * sWr3[lane * 2 + 1] + o1 * sWr3[(lane + 32) * 2 + 1];
#pragma unroll
    for (int m = 1; m < 32; m <<= 1) {
        t3p0 += __shfl_xor_sync(0xffffffffu, t3p0, m);
        t3p1 += __shfl_xor_sync(0xffffffffu, t3p1, m);
        r3p0 += __shfl_xor_sync(0xffffffffu, r3p0, m);
        r3p1 += __shfl_xor_sync(0xffffffffu, r3p1, m);
    }
    if (lane == 0) {
        reinterpret_cast<__half2*>(g_t16)[gw] = __floats2half2_rn(t3p0, t3p1);
        reinterpret_cast<float2*>(g_rbuf)[gw] = make_float2(r3p0 + sb3[0], r3p1 + sb3[1]);
    }
}

// ---------------- L3 gather + pool + last-block softmax ----------------

__global__ void __launch_bounds__(256) k_g2pool(const int* __restrict__ batch,
                                                float* __restrict__ out,
                                                int nblocks) {
    int gw = (blockIdx.x * blockDim.x + threadIdx.x) >> 5;
    int lane = threadIdx.x & 31;
    if (gw < NN) {
        int s0 = g_off[gw], s1 = g_off[gw + 1];
        float ax = 0.f, ay = 0.f;
        const __half2* tv = reinterpret_cast<const __half2*>(g_t16);
        for (int e = s0 + lane; e < s1; e += 32) {
            float2 v = __half22float2(tv[g_csr[e]]);
            ax += v.x; ay += v.y;
        }
#pragma unroll
        for (int m = 1; m < 32; m <<= 1) {
            ax += __shfl_xor_sync(0xffffffffu, ax, m);
            ay += __shfl_xor_sync(0xffffffffu, ay, m);
        }
        if (lane == 0) {
            float inv = 1.f / fmaxf((float)(s1 - s0), 1.f);
            float2 rv = reinterpret_cast<const float2*>(g_rbuf)[gw];
            float hx = fmaxf(ax * inv + rv.x, 0.f);
            float hy = fmaxf(ay * inv + rv.y, 0.f);
            int g = batch[gw];
            atomicAdd(&g_pool[2 * g + 0], hx);
            atomicAdd(&g_pool[2 * g + 1], hy);
            atomicAdd(&g_gcnt[g], 1.f);
        }
    }
    // last-block-done softmax
    __shared__ int last;
    __syncthreads();
    if (threadIdx.x == 0) {
        __threadfence();
        int v = atomicAdd(&g_done, 1);
        last = (v == nblocks - 1) ? 1 : 0;
    }
    __syncthreads();
    if (last) {
        __threadfence();
        int g = threadIdx.x;
        if (g < NG) {
            float c = fmaxf(g_gcnt[g], 1.f);
            float a = g_pool[2 * g + 0] / c;
            float b = g_pool[2 * g + 1] / c;
            float m = fmaxf(a, b);
            float ea = expf(a - m);
            float eb = expf(b - m);
            float s = ea + eb;
            out[2 * g + 0] = ea / s;
            out[2 * g + 1] = eb / s;
        }
        if (threadIdx.x == 0) g_done = 0;
    }
}

extern "C" void kernel_launch(void* const* d_in, const int* in_sizes, int n_in,
                              void* d_out, int out_size) {
    const float* x = (const float*)d_in[0];
    const int* ei = (const int*)d_in[1];
    const int* batch = (const int*)d_in[2];
    const float* Wl0 = (const float*)d_in[3];
    const float* bl0 = (const float*)d_in[4];
    const float* Wr0 = (const float*)d_in[5];
    const float* Wl1 = (const float*)d_in[6];
    const float* bl1 = (const float*)d_in[7];
    const float* Wr1 = (const float*)d_in[8];
    const float* Wl2 = (const float*)d_in[9];
    const float* bl2 = (const float*)d_in[10];
    const float* Wr2 = (const float*)d_in[11];
    const float* Wl3 = (const float*)d_in[12];
    const float* bl3 = (const float*)d_in[13];
    const float* Wr3 = (const float*)d_in[14];
    float* out = (float*)d_out;

    const int* src = ei;
    const int* dst = ei + NE;

    const int TB = 256;
    auto nb = [](long n, int tb) { return (int)((n + tb - 1) / tb); };
    const int GATHER_GRID = nb((long)NN * 32, TB);  // warp per node (12500)

    // CSR build
    k_zero_misc<<<nb(NN, TB), TB>>>();
    k_deg<<<nb(NE, TB), TB>>>(dst);
    k_scan1<<<SCAN_NB, 256>>>();
    k_scan23<<<SCAN_NB, 256>>>();
    k_fill<<<nb(NE, TB), TB>>>(src, dst);

    // L0: 56 -> 16 (pre)
    k_prep0<<<nb(NN, 128), 128>>>(x, Wl0, bl0, Wr0);
    k_g16pre<<<GATHER_GRID, TB>>>();

    // L1: 16 -> 32 (post)
    k_g16post<<<GATHER_GRID, TB>>>(Wl1, bl1, Wr1);

    // L2: 32 -> 64 (post) + fused L3 prep
    k_g32post<<<GATHER_GRID, TB>>>(Wl2, bl2, Wr2, Wl3, bl3, Wr3);

    // L3: gather + pool + softmax (last block)
    k_g2pool<<<GATHER_GRID, TB>>>(batch, out, GATHER_GRID);
}

// round 11
// speedup vs baseline: 1.0452x; 1.0452x over previous
#include <cuda_runtime.h>

#define NN 100000
#define NE 1600000
#define NG 256
#define CAP 64          // padded CSR capacity per node (Poisson(16): overflow ~1e-20)
#define CAPSH 6

// Scratch (static __device__ arrays; zero-initialized at module load; no allocation)
__device__ float g_bufA[NN * 16];    // L0 output
__device__ float g_bufB[NN * 32];    // L1 output
__device__ float g_tbuf[NN * 16];    // L0 scatter operand; later reused for t3 (float2/node)
__device__ float g_rbuf[NN * 16];    // r0 = x@Wr0+b0; later reused for r3 (float2/node)
__device__ int   g_pos[NN];          // degree counter; re-zeroed by k_g2pool each call
__device__ int   g_csr[NN * CAP];    // padded CSR
__device__ float g_pool[NG * 2];     // zeroed (fully!) by k_g32post block 0 each call
__device__ float g_gcnt[NG];
__device__ int   g_done;             // self-resetting

// ---------------- padded CSR build: single kernel, no scan ----------------

__global__ void k_fill(const int* __restrict__ src, const int* __restrict__ dst) {
    int e = blockIdx.x * blockDim.x + threadIdx.x;
    if (e >= NE) return;
    int d = dst[e];
    int p = atomicAdd(&g_pos[d], 1);
    if (p < CAP) g_csr[(d << CAPSH) + p] = src[e];
}

// ---------------- L0 prep: tbuf = x@Wl0, rbuf = x@Wr0 + b0 ----------------

__global__ void k_prep0(const float* __restrict__ x,
                        const float* __restrict__ Wl,
                        const float* __restrict__ bl,
                        const float* __restrict__ Wr) {
    __shared__ float sWl[56 * 16];
    __shared__ float sWr[56 * 16];
    __shared__ float sb[16];
    for (int idx = threadIdx.x; idx < 56 * 16; idx += blockDim.x) {
        sWl[idx] = Wl[idx];
        sWr[idx] = Wr[idx];
    }
    if (threadIdx.x < 16) sb[threadIdx.x] = bl[threadIdx.x];
    __syncthreads();
    int i = blockIdx.x * blockDim.x + threadIdx.x;
    if (i >= NN) return;
    float al[16], ar[16];
#pragma unroll
    for (int j = 0; j < 16; j++) { al[j] = 0.f; ar[j] = sb[j]; }
#pragma unroll 2
    for (int k = 0; k < 56; k++) {
        float hv = x[(size_t)i * 56 + k];
#pragma unroll
        for (int j = 0; j < 16; j++) {
            al[j] += hv * sWl[k * 16 + j];
            ar[j] += hv * sWr[k * 16 + j];
        }
    }
#pragma unroll
    for (int j = 0; j < 16; j++) {
        g_tbuf[(size_t)i * 16 + j] = al[j];
        g_rbuf[(size_t)i * 16 + j] = ar[j];
    }
}

// ---------------- L0 gather (pre, W=16): bufA = relu(agg/deg + r0) ----------------
// lane = (slot:3 | c4:2), 8 edge slots, float4 per lane -> 4 independent LDGs/chunk

__global__ void k_g16pre() {
    int gw = (blockIdx.x * blockDim.x + threadIdx.x) >> 5;
    if (gw >= NN) return;
    int lane = threadIdx.x & 31;
    int c4 = lane & 3;
    int slot = lane >> 2;
    int deg = g_pos[gw];
    int degc = min(deg, CAP);
    const float* __restrict__ t = g_tbuf;
    float4 acc = make_float4(0.f, 0.f, 0.f, 0.f);
    int s0 = gw << CAPSH;
    for (int base = 0; base < degc; base += 32) {
        int idx = base + lane;
        int si = (idx < degc) ? g_csr[s0 + idx] : 0;
        int lim = degc - base;
#pragma unroll
        for (int jb = 0; jb < 32; jb += 8) {
            int j = jb + slot;
            int s = __shfl_sync(0xffffffffu, si, j);
            if (j < lim) {
                float4 v = *reinterpret_cast<const float4*>(t + (size_t)s * 16 + c4 * 4);
                acc.x += v.x; acc.y += v.y; acc.z += v.z; acc.w += v.w;
            }
        }
    }
#pragma unroll
    for (int m = 4; m < 32; m <<= 1) {
        acc.x += __shfl_xor_sync(0xffffffffu, acc.x, m);
        acc.y += __shfl_xor_sync(0xffffffffu, acc.y, m);
        acc.z += __shfl_xor_sync(0xffffffffu, acc.z, m);
        acc.w += __shfl_xor_sync(0xffffffffu, acc.w, m);
    }
    if (lane < 4) {
        float inv = 1.f / fmaxf((float)deg, 1.f);
        float4 rv = *reinterpret_cast<const float4*>(g_rbuf + (size_t)gw * 16 + c4 * 4);
        float4 o;
        o.x = fmaxf(acc.x * inv + rv.x, 0.f);
        o.y = fmaxf(acc.y * inv + rv.y, 0.f);
        o.z = fmaxf(acc.z * inv + rv.z, 0.f);
        o.w = fmaxf(acc.w * inv + rv.w, 0.f);
        *reinterpret_cast<float4*>(g_bufA + (size_t)gw * 16 + c4 * 4) = o;
    }
}

// ---------------- L1 gather (post, 16->32): bufB = relu((agg/deg)@Wl1 + b1 + h@Wr1) ----------------

__global__ void __launch_bounds__(256) k_g16post(const float* __restrict__ Wl,
                                                 const float* __restrict__ bl,
                                                 const float* __restrict__ Wr) {
    __shared__ float sWl[16 * 32];
    __shared__ float sWr[16 * 32];
    __shared__ float sb[32];
    for (int idx = threadIdx.x; idx < 16 * 32; idx += blockDim.x) {
        sWl[idx] = Wl[idx];
        sWr[idx] = Wr[idx];
    }
    if (threadIdx.x < 32) sb[threadIdx.x] = bl[threadIdx.x];
    __syncthreads();
    int gw = (blockIdx.x * blockDim.x + threadIdx.x) >> 5;
    if (gw >= NN) return;
    int lane = threadIdx.x & 31;
    int c4 = lane & 3;
    int slot = lane >> 2;
    int deg = g_pos[gw];
    int degc = min(deg, CAP);
    const float* __restrict__ h = g_bufA;
    float4 acc = make_float4(0.f, 0.f, 0.f, 0.f);
    int s0 = gw << CAPSH;
    for (int base = 0; base < degc; base += 32) {
        int idx = base + lane;
        int si = (idx < degc) ? g_csr[s0 + idx] : 0;
        int lim = degc - base;
#pragma unroll
        for (int jb = 0; jb < 32; jb += 8) {
            int j = jb + slot;
            int s = __shfl_sync(0xffffffffu, si, j);
            if (j < lim) {
                float4 v = *reinterpret_cast<const float4*>(h + (size_t)s * 16 + c4 * 4);
                acc.x += v.x; acc.y += v.y; acc.z += v.z; acc.w += v.w;
            }
        }
    }
#pragma unroll
    for (int m = 4; m < 32; m <<= 1) {
        acc.x += __shfl_xor_sync(0xffffffffu, acc.x, m);
        acc.y += __shfl_xor_sync(0xffffffffu, acc.y, m);
        acc.z += __shfl_xor_sync(0xffffffffu, acc.z, m);
        acc.w += __shfl_xor_sync(0xffffffffu, acc.w, m);
    }
    float inv = 1.f / fmaxf((float)deg, 1.f);
    float hv_mine = (lane < 16) ? h[(size_t)gw * 16 + lane] : 0.f;
    float o = sb[lane];
    float accv[4] = {acc.x, acc.y, acc.z, acc.w};
#pragma unroll
    for (int k = 0; k < 16; k++) {
        float aggk = __shfl_sync(0xffffffffu, accv[k & 3], k >> 2) * inv;
        float hk = __shfl_sync(0xffffffffu, hv_mine, k);
        o += aggk * sWl[k * 32 + lane] + hk * sWr[k * 32 + lane];
    }
    g_bufB[(size_t)gw * 32 + lane] = fmaxf(o, 0.f);
}

// ---------------- L2 gather (post, 32->64) + fused L3 prep + pool-zero ----------------

__global__ void __launch_bounds__(256) k_g32post(const float* __restrict__ Wl,
                                                 const float* __restrict__ bl,
                                                 const float* __restrict__ Wr,
                                                 const float* __restrict__ Wl3,
                                                 const float* __restrict__ bl3,
                                                 const float* __restrict__ Wr3) {
    __shared__ float sWl[32 * 64];
    __shared__ float sWr[32 * 64];
    __shared__ float sb[64];
    __shared__ float sWl3[64 * 2];
    __shared__ float sWr3[64 * 2];
    __shared__ float sb3[2];
    for (int idx = threadIdx.x; idx < 32 * 64; idx += blockDim.x) {
        sWl[idx] = Wl[idx];
        sWr[idx] = Wr[idx];
    }
    if (threadIdx.x < 64) sb[threadIdx.x] = bl[threadIdx.x];
    if (threadIdx.x < 128) { sWl3[threadIdx.x] = Wl3[threadIdx.x]; sWr3[threadIdx.x] = Wr3[threadIdx.x]; }
    if (threadIdx.x < 2) sb3[threadIdx.x] = bl3[threadIdx.x];
    // zero ALL pool buffers for k_g2pool (FIX: strided loops cover NG*2=512 > blockDim)
    if (blockIdx.x == 0) {
        for (int idx = threadIdx.x; idx < NG * 2; idx += blockDim.x) g_pool[idx] = 0.f;
        for (int idx = threadIdx.x; idx < NG; idx += blockDim.x) g_gcnt[idx] = 0.f;
    }
    __syncthreads();
    int gw = (blockIdx.x * blockDim.x + threadIdx.x) >> 5;
    if (gw >= NN) return;
    int lane = threadIdx.x & 31;
    int c4 = lane & 7;    // lane c holds channels c*4..c*4+3
    int slot = lane >> 3; // 4 edge slots
    int deg = g_pos[gw];
    int degc = min(deg, CAP);
    const float* __restrict__ h = g_bufB;
    float4 acc = make_float4(0.f, 0.f, 0.f, 0.f);
    int s0 = gw << CAPSH;
    for (int base = 0; base < degc; base += 32) {
        int idx = base + lane;
        int si = (idx < degc) ? g_csr[s0 + idx] : 0;
        int lim = degc - base;
#pragma unroll
        for (int jb = 0; jb < 32; jb += 4) {
            int j = jb + slot;
            int s = __shfl_sync(0xffffffffu, si, j);
            if (j < lim) {
                float4 v = *reinterpret_cast<const float4*>(h + (size_t)s * 32 + c4 * 4);
                acc.x += v.x; acc.y += v.y; acc.z += v.z; acc.w += v.w;
            }
        }
    }
#pragma unroll
    for (int m = 8; m < 32; m <<= 1) {
        acc.x += __shfl_xor_sync(0xffffffffu, acc.x, m);
        acc.y += __shfl_xor_sync(0xffffffffu, acc.y, m);
        acc.z += __shfl_xor_sync(0xffffffffu, acc.z, m);
        acc.w += __shfl_xor_sync(0xffffffffu, acc.w, m);
    }
    float inv = 1.f / fmaxf((float)deg, 1.f);
    float hv_mine = h[(size_t)gw * 32 + lane];
    float o0 = sb[lane], o1 = sb[lane + 32];
    float accv[4] = {acc.x, acc.y, acc.z, acc.w};
#pragma unroll
    for (int k = 0; k < 32; k++) {
        float aggk = __shfl_sync(0xffffffffu, accv[k & 3], k >> 2) * inv;
        float hk = __shfl_sync(0xffffffffu, hv_mine, k);
        o0 += aggk * sWl[k * 64 + lane] + hk * sWr[k * 64 + lane];
        o1 += aggk * sWl[k * 64 + lane + 32] + hk * sWr[k * 64 + lane + 32];
    }
    o0 = fmaxf(o0, 0.f);
    o1 = fmaxf(o1, 0.f);
    // fused L3 prep: h3[lane] = o0, h3[lane+32] = o1; reduce to t3/r3 (2 wide)
    float t3p0 = o0 * sWl3[lane * 2 + 0] + o1 * sWl3[(lane + 32) * 2 + 0];
    float t3p1 = o0 * sWl3[lane * 2 + 1] + o1 * sWl3[(lane + 32) * 2 + 1];
    float r3p0 = o0 * sWr3[lane * 2 + 0] + o1 * sWr3[(lane + 32) * 2 + 0];
    float r3p1 = o0 * sWr3[lane * 2 + 1] + o1 * sWr3[(lane + 32) * 2 + 1];
#pragma unroll
    for (int m = 1; m < 32; m <<= 1) {
        t3p0 += __shfl_xor_sync(0xffffffffu, t3p0, m);
        t3p1 += __shfl_xor_sync(0xffffffffu, t3p1, m);
        r3p0 += __shfl_xor_sync(0xffffffffu, r3p0, m);
        r3p1 += __shfl_xor_sync(0xffffffffu, r3p1, m);
    }
    if (lane == 0) {
        reinterpret_cast<float2*>(g_tbuf)[gw] = make_float2(t3p0, t3p1);
        reinterpret_cast<float2*>(g_rbuf)[gw] = make_float2(r3p0 + sb3[0], r3p1 + sb3[1]);
    }
}

// ---------------- L3 gather + pool + g_pos reset + last-block softmax ----------------

__global__ void __launch_bounds__(256) k_g2pool(const int* __restrict__ batch,
                                                float* __restrict__ out,
                                                int nblocks) {
    int gw = (blockIdx.x * blockDim.x + threadIdx.x) >> 5;
    int lane = threadIdx.x & 31;
    if (gw < NN) {
        int deg = g_pos[gw];
        int degc = min(deg, CAP);
        int s0 = gw << CAPSH;
        float ax = 0.f, ay = 0.f;
        const float2* tv = reinterpret_cast<const float2*>(g_tbuf);
        for (int e = lane; e < degc; e += 32) {
            float2 v = tv[g_csr[s0 + e]];
            ax += v.x; ay += v.y;
        }
#pragma unroll
        for (int m = 1; m < 32; m <<= 1) {
            ax += __shfl_xor_sync(0xffffffffu, ax, m);
            ay += __shfl_xor_sync(0xffffffffu, ay, m);
        }
        if (lane == 0) {
            g_pos[gw] = 0;  // reset degree counter for the next call
            float inv = 1.f / fmaxf((float)deg, 1.f);
            float2 rv = reinterpret_cast<const float2*>(g_rbuf)[gw];
            float hx = fmaxf(ax * inv + rv.x, 0.f);
            float hy = fmaxf(ay * inv + rv.y, 0.f);
            int g = batch[gw];
            atomicAdd(&g_pool[2 * g + 0], hx);
            atomicAdd(&g_pool[2 * g + 1], hy);
            atomicAdd(&g_gcnt[g], 1.f);
        }
    }
    // last-block-done softmax
    __shared__ int last;
    __syncthreads();
    if (threadIdx.x == 0) {
        __threadfence();
        int v = atomicAdd(&g_done, 1);
        last = (v == nblocks - 1) ? 1 : 0;
    }
    __syncthreads();
    if (last) {
        __threadfence();
        int g = threadIdx.x;
        if (g < NG) {
            float c = fmaxf(g_gcnt[g], 1.f);
            float a = g_pool[2 * g + 0] / c;
            float b = g_pool[2 * g + 1] / c;
            float m = fmaxf(a, b);
            float ea = expf(a - m);
            float eb = expf(b - m);
            float s = ea + eb;
            out[2 * g + 0] = ea / s;
            out[2 * g + 1] = eb / s;
        }
        if (threadIdx.x == 0) g_done = 0;
    }
}

extern "C" void kernel_launch(void* const* d_in, const int* in_sizes, int n_in,
                              void* d_out, int out_size) {
    const float* x = (const float*)d_in[0];
    const int* ei = (const int*)d_in[1];
    const int* batch = (const int*)d_in[2];
    const float* Wl0 = (const float*)d_in[3];
    const float* bl0 = (const float*)d_in[4];
    const float* Wr0 = (const float*)d_in[5];
    const float* Wl1 = (const float*)d_in[6];
    const float* bl1 = (const float*)d_in[7];
    const float* Wr1 = (const float*)d_in[8];
    const float* Wl2 = (const float*)d_in[9];
    const float* bl2 = (const float*)d_in[10];
    const float* Wr2 = (const float*)d_in[11];
    const float* Wl3 = (const float*)d_in[12];
    const float* bl3 = (const float*)d_in[13];
    const float* Wr3 = (const float*)d_in[14];
    float* out = (float*)d_out;

    const int* src = ei;
    const int* dst = ei + NE;

    const int TB = 256;
    auto nb = [](long n, int tb) { return (int)((n + tb - 1) / tb); };
    const int GATHER_GRID = nb((long)NN * 32, TB);  // warp per node (12500)

    // 1. padded CSR build (g_pos zeroed by previous call / initial state)
    k_fill<<<nb(NE, TB), TB>>>(src, dst);
    // 2. L0 prep
    k_prep0<<<nb(NN, 128), 128>>>(x, Wl0, bl0, Wr0);
    // 3. L0 gather (pre)
    k_g16pre<<<GATHER_GRID, TB>>>();
    // 4. L1 gather (post)  <- ncu -s 5 profiles this launch
    k_g16post<<<GATHER_GRID, TB>>>(Wl1, bl1, Wr1);
    // 5. L2 gather (post) + L3 prep + pool-zero
    k_g32post<<<GATHER_GRID, TB>>>(Wl2, bl2, Wr2, Wl3, bl3, Wr3);
    // 6. L3 gather + pool + softmax
    k_g2pool<<<GATHER_GRID, TB>>>(batch, out, GATHER_GRID);
}

// round 12
// speedup vs baseline: 1.0677x; 1.0216x over previous
#include <cuda_runtime.h>

#define NN 100000
#define NE 1600000
#define NG 256
#define CAP 64          // padded CSR capacity per node (Poisson(16): overflow ~1e-20)
#define CAPSH 6

// Scratch (static __device__ arrays; zero-initialized at module load; no allocation)
__device__ float g_bufA[NN * 16];    // L0 output
__device__ float g_bufB[NN * 32];    // L1 output
__device__ float g_tbuf[NN * 16];    // L0 scatter operand; later reused for t3 (float2/node)
__device__ float g_rbuf[NN * 16];    // r0 = x@Wr0+b0; later reused for r3 (float2/node)
__device__ int   g_pos[NN];          // degree counter; re-zeroed by k_g2pool each call
__device__ int   g_csr[NN * CAP];    // padded CSR
__device__ float g_pool[NG * 2];     // zeroed by k_g32post block 0 each call
__device__ float g_gcnt[NG];
__device__ int   g_done;             // self-resetting

// ---------------- padded CSR build: 4 edges/thread for atomic MLP ----------------

__global__ void k_fill(const int* __restrict__ src, const int* __restrict__ dst) {
    const int Q = NE / 4;  // 400000
    int tbase = blockIdx.x * blockDim.x + threadIdx.x;
    if (tbase >= Q) return;
    int e0 = tbase;
    int e1 = tbase + Q;
    int e2 = tbase + 2 * Q;
    int e3 = tbase + 3 * Q;
    int d0 = dst[e0], d1 = dst[e1], d2 = dst[e2], d3 = dst[e3];
    int s0 = src[e0], s1 = src[e1], s2 = src[e2], s3 = src[e3];
    int p0 = atomicAdd(&g_pos[d0], 1);
    int p1 = atomicAdd(&g_pos[d1], 1);
    int p2 = atomicAdd(&g_pos[d2], 1);
    int p3 = atomicAdd(&g_pos[d3], 1);
    if (p0 < CAP) g_csr[(d0 << CAPSH) + p0] = s0;
    if (p1 < CAP) g_csr[(d1 << CAPSH) + p1] = s1;
    if (p2 < CAP) g_csr[(d2 << CAPSH) + p2] = s2;
    if (p3 < CAP) g_csr[(d3 << CAPSH) + p3] = s3;
}

// ---------------- L0 prep: tbuf = x@Wl0, rbuf = x@Wr0 + b0 ----------------

__global__ void k_prep0(const float* __restrict__ x,
                        const float* __restrict__ Wl,
                        const float* __restrict__ bl,
                        const float* __restrict__ Wr) {
    __shared__ float sWl[56 * 16];
    __shared__ float sWr[56 * 16];
    __shared__ float sb[16];
    for (int idx = threadIdx.x; idx < 56 * 16; idx += blockDim.x) {
        sWl[idx] = Wl[idx];
        sWr[idx] = Wr[idx];
    }
    if (threadIdx.x < 16) sb[threadIdx.x] = bl[threadIdx.x];
    __syncthreads();
    int i = blockIdx.x * blockDim.x + threadIdx.x;
    if (i >= NN) return;
    float al[16], ar[16];
#pragma unroll
    for (int j = 0; j < 16; j++) { al[j] = 0.f; ar[j] = sb[j]; }
#pragma unroll 2
    for (int k = 0; k < 56; k++) {
        float hv = x[(size_t)i * 56 + k];
#pragma unroll
        for (int j = 0; j < 16; j++) {
            al[j] += hv * sWl[k * 16 + j];
            ar[j] += hv * sWr[k * 16 + j];
        }
    }
#pragma unroll
    for (int j = 0; j < 16; j++) {
        g_tbuf[(size_t)i * 16 + j] = al[j];
        g_rbuf[(size_t)i * 16 + j] = ar[j];
    }
}

// ---------------- L0 gather (pre, W=16): bufA = relu(agg/deg + r0) ----------------
// lane = (slot:3 | c4:2), 8 edge slots; broadcast loop bound is warp-uniform
// (deg per node), so iterations ~= ceil(deg/8) instead of fixed 4.

__global__ void k_g16pre() {
    int gw = (blockIdx.x * blockDim.x + threadIdx.x) >> 5;
    if (gw >= NN) return;
    int lane = threadIdx.x & 31;
    int c4 = lane & 3;
    int slot = lane >> 2;
    int deg = g_pos[gw];
    int degc = min(deg, CAP);
    const float* __restrict__ t = g_tbuf;
    float4 acc = make_float4(0.f, 0.f, 0.f, 0.f);
    int s0 = gw << CAPSH;
    for (int base = 0; base < degc; base += 32) {
        int idx = base + lane;
        int si = (idx < degc) ? g_csr[s0 + idx] : 0;
        int lim = degc - base;                    // warp-uniform
        int jmax = min(lim, 32);                  // warp-uniform dynamic bound
        for (int jb = 0; jb < jmax; jb += 8) {
            int j = jb + slot;
            int s = __shfl_sync(0xffffffffu, si, j);   // convergent (uniform trip count)
            if (j < lim) {
                float4 v = *reinterpret_cast<const float4*>(t + (size_t)s * 16 + c4 * 4);
                acc.x += v.x; acc.y += v.y; acc.z += v.z; acc.w += v.w;
            }
        }
    }
#pragma unroll
    for (int m = 4; m < 32; m <<= 1) {
        acc.x += __shfl_xor_sync(0xffffffffu, acc.x, m);
        acc.y += __shfl_xor_sync(0xffffffffu, acc.y, m);
        acc.z += __shfl_xor_sync(0xffffffffu, acc.z, m);
        acc.w += __shfl_xor_sync(0xffffffffu, acc.w, m);
    }
    if (lane < 4) {
        float inv = 1.f / fmaxf((float)deg, 1.f);
        float4 rv = *reinterpret_cast<const float4*>(g_rbuf + (size_t)gw * 16 + c4 * 4);
        float4 o;
        o.x = fmaxf(acc.x * inv + rv.x, 0.f);
        o.y = fmaxf(acc.y * inv + rv.y, 0.f);
        o.z = fmaxf(acc.z * inv + rv.z, 0.f);
        o.w = fmaxf(acc.w * inv + rv.w, 0.f);
        *reinterpret_cast<float4*>(g_bufA + (size_t)gw * 16 + c4 * 4) = o;
    }
}

// ---------------- L1 gather (post, 16->32): bufB = relu((agg/deg)@Wl1 + b1 + h@Wr1) ----------------

__global__ void __launch_bounds__(256) k_g16post(const float* __restrict__ Wl,
                                                 const float* __restrict__ bl,
                                                 const float* __restrict__ Wr) {
    __shared__ float sWl[16 * 32];
    __shared__ float sWr[16 * 32];
    __shared__ float sb[32];
    for (int idx = threadIdx.x; idx < 16 * 32; idx += blockDim.x) {
        sWl[idx] = Wl[idx];
        sWr[idx] = Wr[idx];
    }
    if (threadIdx.x < 32) sb[threadIdx.x] = bl[threadIdx.x];
    __syncthreads();
    int gw = (blockIdx.x * blockDim.x + threadIdx.x) >> 5;
    if (gw >= NN) return;
    int lane = threadIdx.x & 31;
    int c4 = lane & 3;
    int slot = lane >> 2;
    int deg = g_pos[gw];
    int degc = min(deg, CAP);
    const float* __restrict__ h = g_bufA;
    float4 acc = make_float4(0.f, 0.f, 0.f, 0.f);
    int s0 = gw << CAPSH;
    for (int base = 0; base < degc; base += 32) {
        int idx = base + lane;
        int si = (idx < degc) ? g_csr[s0 + idx] : 0;
        int lim = degc - base;
        int jmax = min(lim, 32);
        for (int jb = 0; jb < jmax; jb += 8) {
            int j = jb + slot;
            int s = __shfl_sync(0xffffffffu, si, j);
            if (j < lim) {
                float4 v = *reinterpret_cast<const float4*>(h + (size_t)s * 16 + c4 * 4);
                acc.x += v.x; acc.y += v.y; acc.z += v.z; acc.w += v.w;
            }
        }
    }
#pragma unroll
    for (int m = 4; m < 32; m <<= 1) {
        acc.x += __shfl_xor_sync(0xffffffffu, acc.x, m);
        acc.y += __shfl_xor_sync(0xffffffffu, acc.y, m);
        acc.z += __shfl_xor_sync(0xffffffffu, acc.z, m);
        acc.w += __shfl_xor_sync(0xffffffffu, acc.w, m);
    }
    float inv = 1.f / fmaxf((float)deg, 1.f);
    float hv_mine = (lane < 16) ? h[(size_t)gw * 16 + lane] : 0.f;
    float o = sb[lane];
    float accv[4] = {acc.x, acc.y, acc.z, acc.w};
#pragma unroll
    for (int k = 0; k < 16; k++) {
        float aggk = __shfl_sync(0xffffffffu, accv[k & 3], k >> 2) * inv;
        float hk = __shfl_sync(0xffffffffu, hv_mine, k);
        o += aggk * sWl[k * 32 + lane] + hk * sWr[k * 32 + lane];
    }
    g_bufB[(size_t)gw * 32 + lane] = fmaxf(o, 0.f);
}

// ---------------- L2 gather (post, 32->64) + fused L3 prep + pool-zero ----------------

__global__ void __launch_bounds__(256) k_g32post(const float* __restrict__ Wl,
                                                 const float* __restrict__ bl,
                                                 const float* __restrict__ Wr,
                                                 const float* __restrict__ Wl3,
                                                 const float* __restrict__ bl3,
                                                 const float* __restrict__ Wr3) {
    __shared__ float sWl[32 * 64];
    __shared__ float sWr[32 * 64];
    __shared__ float sb[64];
    __shared__ float sWl3[64 * 2];
    __shared__ float sWr3[64 * 2];
    __shared__ float sb3[2];
    for (int idx = threadIdx.x; idx < 32 * 64; idx += blockDim.x) {
        sWl[idx] = Wl[idx];
        sWr[idx] = Wr[idx];
    }
    if (threadIdx.x < 64) sb[threadIdx.x] = bl[threadIdx.x];
    if (threadIdx.x < 128) { sWl3[threadIdx.x] = Wl3[threadIdx.x]; sWr3[threadIdx.x] = Wr3[threadIdx.x]; }
    if (threadIdx.x < 2) sb3[threadIdx.x] = bl3[threadIdx.x];
    // zero ALL pool buffers for k_g2pool (strided loops cover NG*2 = 512)
    if (blockIdx.x == 0) {
        for (int idx = threadIdx.x; idx < NG * 2; idx += blockDim.x) g_pool[idx] = 0.f;
        for (int idx = threadIdx.x; idx < NG; idx += blockDim.x) g_gcnt[idx] = 0.f;
    }
    __syncthreads();
    int gw = (blockIdx.x * blockDim.x + threadIdx.x) >> 5;
    if (gw >= NN) return;
    int lane = threadIdx.x & 31;
    int c4 = lane & 7;    // lane c holds channels c*4..c*4+3
    int slot = lane >> 3; // 4 edge slots
    int deg = g_pos[gw];
    int degc = min(deg, CAP);
    const float* __restrict__ h = g_bufB;
    float4 acc = make_float4(0.f, 0.f, 0.f, 0.f);
    int s0 = gw << CAPSH;
    for (int base = 0; base < degc; base += 32) {
        int idx = base + lane;
        int si = (idx < degc) ? g_csr[s0 + idx] : 0;
        int lim = degc - base;
        int jmax = min(lim, 32);
        for (int jb = 0; jb < jmax; jb += 4) {
            int j = jb + slot;
            int s = __shfl_sync(0xffffffffu, si, j);
            if (j < lim) {
                float4 v = *reinterpret_cast<const float4*>(h + (size_t)s * 32 + c4 * 4);
                acc.x += v.x; acc.y += v.y; acc.z += v.z; acc.w += v.w;
            }
        }
    }
#pragma unroll
    for (int m = 8; m < 32; m <<= 1) {
        acc.x += __shfl_xor_sync(0xffffffffu, acc.x, m);
        acc.y += __shfl_xor_sync(0xffffffffu, acc.y, m);
        acc.z += __shfl_xor_sync(0xffffffffu, acc.z, m);
        acc.w += __shfl_xor_sync(0xffffffffu, acc.w, m);
    }
    float inv = 1.f / fmaxf((float)deg, 1.f);
    float hv_mine = h[(size_t)gw * 32 + lane];
    float o0 = sb[lane], o1 = sb[lane + 32];
    float accv[4] = {acc.x, acc.y, acc.z, acc.w};
#pragma unroll
    for (int k = 0; k < 32; k++) {
        float aggk = __shfl_sync(0xffffffffu, accv[k & 3], k >> 2) * inv;
        float hk = __shfl_sync(0xffffffffu, hv_mine, k);
        o0 += aggk * sWl[k * 64 + lane] + hk * sWr[k * 64 + lane];
        o1 += aggk * sWl[k * 64 + lane + 32] + hk * sWr[k * 64 + lane + 32];
    }
    o0 = fmaxf(o0, 0.f);
    o1 = fmaxf(o1, 0.f);
    // fused L3 prep: h3[lane] = o0, h3[lane+32] = o1; reduce to t3/r3 (2 wide)
    float t3p0 = o0 * sWl3[lane * 2 + 0] + o1 * sWl3[(lane + 32) * 2 + 0];
    float t3p1 = o0 * sWl3[lane * 2 + 1] + o1 * sWl3[(lane + 32) * 2 + 1];
    float r3p0 = o0 * sWr3[lane * 2 + 0] + o1 * sWr3[(lane + 32) * 2 + 0];
    float r3p1 = o0 * sWr3[lane * 2 + 1] + o1 * sWr3[(lane + 32) * 2 + 1];
#pragma unroll
    for (int m = 1; m < 32; m <<= 1) {
        t3p0 += __shfl_xor_sync(0xffffffffu, t3p0, m);
        t3p1 += __shfl_xor_sync(0xffffffffu, t3p1, m);
        r3p0 += __shfl_xor_sync(0xffffffffu, r3p0, m);
        r3p1 += __shfl_xor_sync(0xffffffffu, r3p1, m);
    }
    if (lane == 0) {
        reinterpret_cast<float2*>(g_tbuf)[gw] = make_float2(t3p0, t3p1);
        reinterpret_cast<float2*>(g_rbuf)[gw] = make_float2(r3p0 + sb3[0], r3p1 + sb3[1]);
    }
}

// ---------------- L3 gather + pool + g_pos reset + last-block softmax ----------------

__global__ void __launch_bounds__(256) k_g2pool(const int* __restrict__ batch,
                                                float* __restrict__ out,
                                                int nblocks) {
    int gw = (blockIdx.x * blockDim.x + threadIdx.x) >> 5;
    int lane = threadIdx.x & 31;
    if (gw < NN) {
        int deg = g_pos[gw];
        int degc = min(deg, CAP);
        int s0 = gw << CAPSH;
        float ax = 0.f, ay = 0.f;
        const float2* tv = reinterpret_cast<const float2*>(g_tbuf);
        for (int e = lane; e < degc; e += 32) {
            float2 v = tv[g_csr[s0 + e]];
            ax += v.x; ay += v.y;
        }
#pragma unroll
        for (int m = 1; m < 32; m <<= 1) {
            ax += __shfl_xor_sync(0xffffffffu, ax, m);
            ay += __shfl_xor_sync(0xffffffffu, ay, m);
        }
        if (lane == 0) {
            g_pos[gw] = 0;  // reset degree counter for the next call
            float inv = 1.f / fmaxf((float)deg, 1.f);
            float2 rv = reinterpret_cast<const float2*>(g_rbuf)[gw];
            float hx = fmaxf(ax * inv + rv.x, 0.f);
            float hy = fmaxf(ay * inv + rv.y, 0.f);
            int g = batch[gw];
            atomicAdd(&g_pool[2 * g + 0], hx);
            atomicAdd(&g_pool[2 * g + 1], hy);
            atomicAdd(&g_gcnt[g], 1.f);
        }
    }
    // last-block-done softmax
    __shared__ int last;
    __syncthreads();
    if (threadIdx.x == 0) {
        __threadfence();
        int v = atomicAdd(&g_done, 1);
        last = (v == nblocks - 1) ? 1 : 0;
    }
    __syncthreads();
    if (last) {
        __threadfence();
        int g = threadIdx.x;
        if (g < NG) {
            float c = fmaxf(g_gcnt[g], 1.f);
            float a = g_pool[2 * g + 0] / c;
            float b = g_pool[2 * g + 1] / c;
            float m = fmaxf(a, b);
            float ea = expf(a - m);
            float eb = expf(b - m);
            float s = ea + eb;
            out[2 * g + 0] = ea / s;
            out[2 * g + 1] = eb / s;
        }
        if (threadIdx.x == 0) g_done = 0;
    }
}

extern "C" void kernel_launch(void* const* d_in, const int* in_sizes, int n_in,
                              void* d_out, int out_size) {
    const float* x = (const float*)d_in[0];
    const int* ei = (const int*)d_in[1];
    const int* batch = (const int*)d_in[2];
    const float* Wl0 = (const float*)d_in[3];
    const float* bl0 = (const float*)d_in[4];
    const float* Wr0 = (const float*)d_in[5];
    const float* Wl1 = (const float*)d_in[6];
    const float* bl1 = (const float*)d_in[7];
    const float* Wr1 = (const float*)d_in[8];
    const float* Wl2 = (const float*)d_in[9];
    const float* bl2 = (const float*)d_in[10];
    const float* Wr2 = (const float*)d_in[11];
    const float* Wl3 = (const float*)d_in[12];
    const float* bl3 = (const float*)d_in[13];
    const float* Wr3 = (const float*)d_in[14];
    float* out = (float*)d_out;

    const int* src = ei;
    const int* dst = ei + NE;

    const int TB = 256;
    auto nb = [](long n, int tb) { return (int)((n + tb - 1) / tb); };
    const int GATHER_GRID = nb((long)NN * 32, TB);  // warp per node (12500)

    // 1. padded CSR build (4 edges/thread, g_pos zeroed by previous call)
    k_fill<<<nb(NE / 4, TB), TB>>>(src, dst);
    // 2. L0 prep
    k_prep0<<<nb(NN, 128), 128>>>(x, Wl0, bl0, Wr0);
    // 3. L0 gather (pre)
    k_g16pre<<<GATHER_GRID, TB>>>();
    // 4. L1 gather (post)  <- ncu -s 5 profiles this launch
    k_g16post<<<GATHER_GRID, TB>>>(Wl1, bl1, Wr1);
    // 5. L2 gather (post) + L3 prep + pool-zero
    k_g32post<<<GATHER_GRID, TB>>>(Wl2, bl2, Wr2, Wl3, bl3, Wr3);
    // 6. L3 gather + pool + softmax
    k_g2pool<<<GATHER_GRID, TB>>>(batch, out, GATHER_GRID);
}

// round 13
// speedup vs baseline: 1.2084x; 1.1317x over previous
#include <cuda_runtime.h>

#define NN 100000
#define NE 1600000
#define NG 256
#define CAP 64          // padded CSR capacity per node (Poisson(16): overflow ~1e-20)
#define CAPSH 6

// Scratch (static __device__ arrays; zero-initialized at module load; no allocation)
__device__ float g_bufA[NN * 16];    // L0 output
__device__ float g_bufB[NN * 32];    // L1 output
__device__ float g_agg[NN * 32];     // raw neighbor sums (16w for L1, 32w for L2)
__device__ float g_tbuf[NN * 16];    // t0 (16w); later t3 (float2/node)
__device__ float g_rbuf[NN * 16];    // r0 (16w); later r3 (float2/node)
__device__ int   g_pos[NN];          // degree counter; re-zeroed by k_g2pool each call
__device__ int   g_csr[NN * CAP];    // padded CSR
__device__ float g_pool[NG * 2];     // zeroed by k_update2 block 0 each call
__device__ float g_gcnt[NG];
__device__ int   g_done;             // self-resetting

// ---------------- padded CSR build: 4 edges/thread for atomic MLP ----------------

__global__ void k_fill(const int* __restrict__ src, const int* __restrict__ dst) {
    const int Q = NE / 4;
    int tbase = blockIdx.x * blockDim.x + threadIdx.x;
    if (tbase >= Q) return;
    int e0 = tbase, e1 = tbase + Q, e2 = tbase + 2 * Q, e3 = tbase + 3 * Q;
    int d0 = dst[e0], d1 = dst[e1], d2 = dst[e2], d3 = dst[e3];
    int s0 = src[e0], s1 = src[e1], s2 = src[e2], s3 = src[e3];
    int p0 = atomicAdd(&g_pos[d0], 1);
    int p1 = atomicAdd(&g_pos[d1], 1);
    int p2 = atomicAdd(&g_pos[d2], 1);
    int p3 = atomicAdd(&g_pos[d3], 1);
    if (p0 < CAP) g_csr[(d0 << CAPSH) + p0] = s0;
    if (p1 < CAP) g_csr[(d1 << CAPSH) + p1] = s1;
    if (p2 < CAP) g_csr[(d2 << CAPSH) + p2] = s2;
    if (p3 < CAP) g_csr[(d3 << CAPSH) + p3] = s3;
}

// ---------------- L0 prep: tbuf = x@Wl0, rbuf = x@Wr0 + b0 ----------------

__global__ void k_prep0(const float* __restrict__ x,
                        const float* __restrict__ Wl,
                        const float* __restrict__ bl,
                        const float* __restrict__ Wr) {
    __shared__ float sWl[56 * 16];
    __shared__ float sWr[56 * 16];
    __shared__ float sb[16];
    for (int idx = threadIdx.x; idx < 56 * 16; idx += blockDim.x) {
        sWl[idx] = Wl[idx];
        sWr[idx] = Wr[idx];
    }
    if (threadIdx.x < 16) sb[threadIdx.x] = bl[threadIdx.x];
    __syncthreads();
    int i = blockIdx.x * blockDim.x + threadIdx.x;
    if (i >= NN) return;
    float al[16], ar[16];
#pragma unroll
    for (int j = 0; j < 16; j++) { al[j] = 0.f; ar[j] = sb[j]; }
#pragma unroll 2
    for (int k = 0; k < 56; k++) {
        float hv = x[(size_t)i * 56 + k];
#pragma unroll
        for (int j = 0; j < 16; j++) {
            al[j] += hv * sWl[k * 16 + j];
            ar[j] += hv * sWr[k * 16 + j];
        }
    }
#pragma unroll
    for (int j = 0; j < 16; j++) {
        g_tbuf[(size_t)i * 16 + j] = al[j];
        g_rbuf[(size_t)i * 16 + j] = ar[j];
    }
}

// ---------------- L0 gather (pre, W=16): bufA = relu(agg/deg + r0) ----------------

__global__ void k_g16pre() {
    int gw = (blockIdx.x * blockDim.x + threadIdx.x) >> 5;
    if (gw >= NN) return;
    int lane = threadIdx.x & 31;
    int c4 = lane & 3;
    int slot = lane >> 2;
    int deg = g_pos[gw];
    int degc = min(deg, CAP);
    const float* __restrict__ t = g_tbuf;
    float4 acc = make_float4(0.f, 0.f, 0.f, 0.f);
    int s0 = gw << CAPSH;
    for (int base = 0; base < degc; base += 32) {
        int idx = base + lane;
        int si = (idx < degc) ? g_csr[s0 + idx] : 0;
        int lim = degc - base;
        int jmax = min(lim, 32);
        for (int jb = 0; jb < jmax; jb += 8) {
            int j = jb + slot;
            int s = __shfl_sync(0xffffffffu, si, j);
            if (j < lim) {
                float4 v = *reinterpret_cast<const float4*>(t + (size_t)s * 16 + c4 * 4);
                acc.x += v.x; acc.y += v.y; acc.z += v.z; acc.w += v.w;
            }
        }
    }
#pragma unroll
    for (int m = 4; m < 32; m <<= 1) {
        acc.x += __shfl_xor_sync(0xffffffffu, acc.x, m);
        acc.y += __shfl_xor_sync(0xffffffffu, acc.y, m);
        acc.z += __shfl_xor_sync(0xffffffffu, acc.z, m);
        acc.w += __shfl_xor_sync(0xffffffffu, acc.w, m);
    }
    if (lane < 4) {
        float inv = 1.f / fmaxf((float)deg, 1.f);
        float4 rv = *reinterpret_cast<const float4*>(g_rbuf + (size_t)gw * 16 + c4 * 4);
        float4 o;
        o.x = fmaxf(acc.x * inv + rv.x, 0.f);
        o.y = fmaxf(acc.y * inv + rv.y, 0.f);
        o.z = fmaxf(acc.z * inv + rv.z, 0.f);
        o.w = fmaxf(acc.w * inv + rv.w, 0.f);
        *reinterpret_cast<float4*>(g_bufA + (size_t)gw * 16 + c4 * 4) = o;
    }
}

// ---------------- L1 gather-only (W=16): g_agg[gw] = sum of bufA[neighbors] ----------------

__global__ void k_g16agg() {
    int gw = (blockIdx.x * blockDim.x + threadIdx.x) >> 5;
    if (gw >= NN) return;
    int lane = threadIdx.x & 31;
    int c4 = lane & 3;
    int slot = lane >> 2;
    int degc = min(g_pos[gw], CAP);
    const float* __restrict__ h = g_bufA;
    float4 acc = make_float4(0.f, 0.f, 0.f, 0.f);
    int s0 = gw << CAPSH;
    for (int base = 0; base < degc; base += 32) {
        int idx = base + lane;
        int si = (idx < degc) ? g_csr[s0 + idx] : 0;
        int lim = degc - base;
        int jmax = min(lim, 32);
        for (int jb = 0; jb < jmax; jb += 8) {
            int j = jb + slot;
            int s = __shfl_sync(0xffffffffu, si, j);
            if (j < lim) {
                float4 v = *reinterpret_cast<const float4*>(h + (size_t)s * 16 + c4 * 4);
                acc.x += v.x; acc.y += v.y; acc.z += v.z; acc.w += v.w;
            }
        }
    }
#pragma unroll
    for (int m = 4; m < 32; m <<= 1) {
        acc.x += __shfl_xor_sync(0xffffffffu, acc.x, m);
        acc.y += __shfl_xor_sync(0xffffffffu, acc.y, m);
        acc.z += __shfl_xor_sync(0xffffffffu, acc.z, m);
        acc.w += __shfl_xor_sync(0xffffffffu, acc.w, m);
    }
    if (lane < 4)
        *reinterpret_cast<float4*>(g_agg + (size_t)gw * 16 + c4 * 4) = acc;
}

// ---------------- L1 update (thread/node): bufB = relu((agg/deg)@Wl1 + b1 + bufA@Wr1) ----------------

__global__ void __launch_bounds__(128) k_update1(const float* __restrict__ Wl,
                                                 const float* __restrict__ bl,
                                                 const float* __restrict__ Wr) {
    __shared__ float sWl[16 * 32];
    __shared__ float sWr[16 * 32];
    __shared__ float sb[32];
    for (int idx = threadIdx.x; idx < 16 * 32; idx += blockDim.x) {
        sWl[idx] = Wl[idx];
        sWr[idx] = Wr[idx];
    }
    if (threadIdx.x < 32) sb[threadIdx.x] = bl[threadIdx.x];
    __syncthreads();
    int i = blockIdx.x * blockDim.x + threadIdx.x;
    if (i >= NN) return;
    float inv = 1.f / fmaxf((float)g_pos[i], 1.f);
    float acc[32];
#pragma unroll
    for (int j = 0; j < 32; j++) acc[j] = sb[j];
#pragma unroll 2
    for (int k = 0; k < 16; k++) {
        float a = g_agg[(size_t)i * 16 + k] * inv;
        float hv = g_bufA[(size_t)i * 16 + k];
#pragma unroll
        for (int j = 0; j < 32; j++)
            acc[j] += a * sWl[k * 32 + j] + hv * sWr[k * 32 + j];
    }
#pragma unroll
    for (int j = 0; j < 32; j++)
        g_bufB[(size_t)i * 32 + j] = fmaxf(acc[j], 0.f);
}

// ---------------- L2 gather-only (W=32): g_agg[gw] = sum of bufB[neighbors] ----------------

__global__ void k_g32agg() {
    int gw = (blockIdx.x * blockDim.x + threadIdx.x) >> 5;
    if (gw >= NN) return;
    int lane = threadIdx.x & 31;
    int c4 = lane & 7;
    int slot = lane >> 3;
    int degc = min(g_pos[gw], CAP);
    const float* __restrict__ h = g_bufB;
    float4 acc = make_float4(0.f, 0.f, 0.f, 0.f);
    int s0 = gw << CAPSH;
    for (int base = 0; base < degc; base += 32) {
        int idx = base + lane;
        int si = (idx < degc) ? g_csr[s0 + idx] : 0;
        int lim = degc - base;
        int jmax = min(lim, 32);
        for (int jb = 0; jb < jmax; jb += 4) {
            int j = jb + slot;
            int s = __shfl_sync(0xffffffffu, si, j);
            if (j < lim) {
                float4 v = *reinterpret_cast<const float4*>(h + (size_t)s * 32 + c4 * 4);
                acc.x += v.x; acc.y += v.y; acc.z += v.z; acc.w += v.w;
            }
        }
    }
#pragma unroll
    for (int m = 8; m < 32; m <<= 1) {
        acc.x += __shfl_xor_sync(0xffffffffu, acc.x, m);
        acc.y += __shfl_xor_sync(0xffffffffu, acc.y, m);
        acc.z += __shfl_xor_sync(0xffffffffu, acc.z, m);
        acc.w += __shfl_xor_sync(0xffffffffu, acc.w, m);
    }
    if (lane < 8)
        *reinterpret_cast<float4*>(g_agg + (size_t)gw * 32 + c4 * 4) = acc;
}

// ---------------- L2 update (thread/node) + fused L3 prep + pool-zero ----------------
// h3 = relu((agg/deg)@Wl2 + b2 + bufB@Wr2) computed in two 32-channel halves,
// folded immediately into t3 = h3@Wl3, r3 = h3@Wr3 + b3 (4 scalars/node).

__global__ void __launch_bounds__(128) k_update2(const float* __restrict__ Wl,
                                                 const float* __restrict__ bl,
                                                 const float* __restrict__ Wr,
                                                 const float* __restrict__ Wl3,
                                                 const float* __restrict__ bl3,
                                                 const float* __restrict__ Wr3) {
    __shared__ float sWl[32 * 64];
    __shared__ float sWr[32 * 64];
    __shared__ float sb[64];
    __shared__ float sWl3[64 * 2];
    __shared__ float sWr3[64 * 2];
    __shared__ float sb3[2];
    for (int idx = threadIdx.x; idx < 32 * 64; idx += blockDim.x) {
        sWl[idx] = Wl[idx];
        sWr[idx] = Wr[idx];
    }
    if (threadIdx.x < 64) sb[threadIdx.x] = bl[threadIdx.x];
    if (threadIdx.x < 128) { sWl3[threadIdx.x] = Wl3[threadIdx.x]; sWr3[threadIdx.x] = Wr3[threadIdx.x]; }
    if (threadIdx.x < 2) sb3[threadIdx.x] = bl3[threadIdx.x];
    // zero ALL pool buffers for k_g2pool (strided; covers NG*2 = 512)
    if (blockIdx.x == 0) {
        for (int idx = threadIdx.x; idx < NG * 2; idx += blockDim.x) g_pool[idx] = 0.f;
        for (int idx = threadIdx.x; idx < NG; idx += blockDim.x) g_gcnt[idx] = 0.f;
    }
    __syncthreads();
    int i = blockIdx.x * blockDim.x + threadIdx.x;
    if (i >= NN) return;
    float inv = 1.f / fmaxf((float)g_pos[i], 1.f);
    float t3p0 = 0.f, t3p1 = 0.f, r3p0 = 0.f, r3p1 = 0.f;
    for (int half = 0; half < 2; half++) {
        float acc[32];
#pragma unroll
        for (int j = 0; j < 32; j++) acc[j] = sb[half * 32 + j];
#pragma unroll 2
        for (int k = 0; k < 32; k++) {
            float a = g_agg[(size_t)i * 32 + k] * inv;
            float hv = g_bufB[(size_t)i * 32 + k];
#pragma unroll
            for (int j = 0; j < 32; j++)
                acc[j] += a * sWl[k * 64 + half * 32 + j] + hv * sWr[k * 64 + half * 32 + j];
        }
#pragma unroll
        for (int j = 0; j < 32; j++) {
            float h3 = fmaxf(acc[j], 0.f);
            int ch = half * 32 + j;
            t3p0 += h3 * sWl3[ch * 2 + 0];
            t3p1 += h3 * sWl3[ch * 2 + 1];
            r3p0 += h3 * sWr3[ch * 2 + 0];
            r3p1 += h3 * sWr3[ch * 2 + 1];
        }
    }
    reinterpret_cast<float2*>(g_tbuf)[i] = make_float2(t3p0, t3p1);
    reinterpret_cast<float2*>(g_rbuf)[i] = make_float2(r3p0 + sb3[0], r3p1 + sb3[1]);
}

// ---------------- L3 gather + pool (2 nodes/warp) + g_pos reset + last-block softmax ----------------

__global__ void __launch_bounds__(256) k_g2pool(const int* __restrict__ batch,
                                                float* __restrict__ out,
                                                int nblocks) {
    int w = (blockIdx.x * blockDim.x + threadIdx.x) >> 5;
    int lane = threadIdx.x & 31;
    int half = lane >> 4;
    int sub = lane & 15;
    int gw = w * 2 + half;
    float ax = 0.f, ay = 0.f;
    int deg = 0;
    if (gw < NN) {
        deg = g_pos[gw];
        int degc = min(deg, CAP);
        int s0 = gw << CAPSH;
        const float2* tv = reinterpret_cast<const float2*>(g_tbuf);
        for (int e = sub; e < degc; e += 16) {
            float2 v = tv[g_csr[s0 + e]];
            ax += v.x; ay += v.y;
        }
    }
    // 16-lane sub-reduction (xor m<16 keeps halves independent); convergent
#pragma unroll
    for (int m = 1; m < 16; m <<= 1) {
        ax += __shfl_xor_sync(0xffffffffu, ax, m);
        ay += __shfl_xor_sync(0xffffffffu, ay, m);
    }
    if (gw < NN && sub == 0) {
        g_pos[gw] = 0;  // reset degree counter for the next call
        float inv = 1.f / fmaxf((float)deg, 1.f);
        float2 rv = reinterpret_cast<const float2*>(g_rbuf)[gw];
        float hx = fmaxf(ax * inv + rv.x, 0.f);
        float hy = fmaxf(ay * inv + rv.y, 0.f);
        int g = batch[gw];
        atomicAdd(&g_pool[2 * g + 0], hx);
        atomicAdd(&g_pool[2 * g + 1], hy);
        atomicAdd(&g_gcnt[g], 1.f);
    }
    // last-block-done softmax
    __shared__ int last;
    __syncthreads();
    if (threadIdx.x == 0) {
        __threadfence();
        int v = atomicAdd(&g_done, 1);
        last = (v == nblocks - 1) ? 1 : 0;
    }
    __syncthreads();
    if (last) {
        __threadfence();
        int g = threadIdx.x;
        if (g < NG) {
            float c = fmaxf(g_gcnt[g], 1.f);
            float a = g_pool[2 * g + 0] / c;
            float b = g_pool[2 * g + 1] / c;
            float m = fmaxf(a, b);
            float ea = expf(a - m);
            float eb = expf(b - m);
            float s = ea + eb;
            out[2 * g + 0] = ea / s;
            out[2 * g + 1] = eb / s;
        }
        if (threadIdx.x == 0) g_done = 0;
    }
}

extern "C" void kernel_launch(void* const* d_in, const int* in_sizes, int n_in,
                              void* d_out, int out_size) {
    const float* x = (const float*)d_in[0];
    const int* ei = (const int*)d_in[1];
    const int* batch = (const int*)d_in[2];
    const float* Wl0 = (const float*)d_in[3];
    const float* bl0 = (const float*)d_in[4];
    const float* Wr0 = (const float*)d_in[5];
    const float* Wl1 = (const float*)d_in[6];
    const float* bl1 = (const float*)d_in[7];
    const float* Wr1 = (const float*)d_in[8];
    const float* Wl2 = (const float*)d_in[9];
    const float* bl2 = (const float*)d_in[10];
    const float* Wr2 = (const float*)d_in[11];
    const float* Wl3 = (const float*)d_in[12];
    const float* bl3 = (const float*)d_in[13];
    const float* Wr3 = (const float*)d_in[14];
    float* out = (float*)d_out;

    const int* src = ei;
    const int* dst = ei + NE;

    const int TB = 256;
    auto nb = [](long n, int tb) { return (int)((n + tb - 1) / tb); };
    const int GATHER_GRID = nb((long)NN * 32, TB);       // warp per node (12500)
    const int POOL_GRID = nb((long)NN * 16, TB);         // 2 nodes per warp (6250)

    // 1. padded CSR build
    k_fill<<<nb(NE / 4, TB), TB>>>(src, dst);
    // 2. L0 prep
    k_prep0<<<nb(NN, 128), 128>>>(x, Wl0, bl0, Wr0);
    // 3. L0 gather (pre, fused elementwise epilogue)
    k_g16pre<<<GATHER_GRID, TB>>>();
    // 4. L1 gather-only
    k_g16agg<<<GATHER_GRID, TB>>>();
    // 5. L1 update (thread/node matvec)
    k_update1<<<nb(NN, 128), 128>>>(Wl1, bl1, Wr1);
    // 6. L2 gather-only
    k_g32agg<<<GATHER_GRID, TB>>>();
    // 7. L2 update + fused L3 prep + pool-zero
    k_update2<<<nb(NN, 128), 128>>>(Wl2, bl2, Wr2, Wl3, bl3, Wr3);
    // 8. L3 gather + pool + softmax
    k_g2pool<<<POOL_GRID, TB>>>(batch, out, POOL_GRID);
}

// round 14
// speedup vs baseline: 1.2614x; 1.0439x over previous
#include <cuda_runtime.h>

#define NN 100000
#define NE 1600000
#define NG 256
#define CAP 64          // padded CSR capacity per node (Poisson(16): overflow ~1e-20)
#define CAPSH 6
#define FILL_BLOCKS 1563   // ceil((NE/4)/256)
#define PREP_BLOCKS 391    // ceil(NN/256)

// Scratch (static __device__ arrays; zero-initialized at module load; no allocation)
__device__ float g_bufA[NN * 16];    // L0 output
__device__ float g_bufB[NN * 32];    // L1 output
__device__ float g_agg[NN * 32];     // raw neighbor sums (16w for L1, 32w for L2)
__device__ float g_tbuf[NN * 16];    // t0 (16w); later t3 (float2/node)
__device__ float g_rbuf[NN * 16];    // r0 (16w); later r3 (float2/node)
__device__ int   g_pos[NN];          // degree counter; re-zeroed by k_g2pool each call
__device__ int   g_csr[NN * CAP];    // padded CSR
__device__ float g_pool[NG * 2];     // zeroed by k_update2 block 0 each call
__device__ float g_gcnt[NG];
__device__ int   g_done;             // self-resetting

// ---------------- fused CSR build + L0 prep (independent work, one launch) ----------------

__global__ void __launch_bounds__(256) k_fillprep(
        const int* __restrict__ src, const int* __restrict__ dst,
        const float* __restrict__ x,
        const float* __restrict__ Wl, const float* __restrict__ bl,
        const float* __restrict__ Wr) {
    __shared__ float sWl[56 * 16];
    __shared__ float sWr[56 * 16];
    __shared__ float sb[16];
    if (blockIdx.x < FILL_BLOCKS) {
        // ---- CSR fill: 4 strided edges/thread for atomic MLP ----
        const int Q = NE / 4;
        int tbase = blockIdx.x * blockDim.x + threadIdx.x;
        if (tbase >= Q) return;
        int e0 = tbase, e1 = tbase + Q, e2 = tbase + 2 * Q, e3 = tbase + 3 * Q;
        int d0 = dst[e0], d1 = dst[e1], d2 = dst[e2], d3 = dst[e3];
        int s0 = src[e0], s1 = src[e1], s2 = src[e2], s3 = src[e3];
        int p0 = atomicAdd(&g_pos[d0], 1);
        int p1 = atomicAdd(&g_pos[d1], 1);
        int p2 = atomicAdd(&g_pos[d2], 1);
        int p3 = atomicAdd(&g_pos[d3], 1);
        if (p0 < CAP) g_csr[(d0 << CAPSH) + p0] = s0;
        if (p1 < CAP) g_csr[(d1 << CAPSH) + p1] = s1;
        if (p2 < CAP) g_csr[(d2 << CAPSH) + p2] = s2;
        if (p3 < CAP) g_csr[(d3 << CAPSH) + p3] = s3;
    } else {
        // ---- L0 prep: tbuf = x@Wl0, rbuf = x@Wr0 + b0 ----
        for (int idx = threadIdx.x; idx < 56 * 16; idx += blockDim.x) {
            sWl[idx] = Wl[idx];
            sWr[idx] = Wr[idx];
        }
        if (threadIdx.x < 16) sb[threadIdx.x] = bl[threadIdx.x];
        __syncthreads();
        int i = (blockIdx.x - FILL_BLOCKS) * blockDim.x + threadIdx.x;
        if (i >= NN) return;
        float al[16], ar[16];
#pragma unroll
        for (int j = 0; j < 16; j++) { al[j] = 0.f; ar[j] = sb[j]; }
#pragma unroll 2
        for (int k = 0; k < 56; k++) {
            float hv = x[(size_t)i * 56 + k];
#pragma unroll
            for (int j = 0; j < 16; j++) {
                al[j] += hv * sWl[k * 16 + j];
                ar[j] += hv * sWr[k * 16 + j];
            }
        }
#pragma unroll
        for (int j = 0; j < 16; j++) {
            g_tbuf[(size_t)i * 16 + j] = al[j];
            g_rbuf[(size_t)i * 16 + j] = ar[j];
        }
    }
}

// ---------------- gather cores ----------------
// W=16: lane = (slot:3 | c4:2). Common case deg<=32: straight-line chunk with
// PAIRED slots (2 shfls + 2 independent float4 loads per iteration -> MLP 2).
// Rare deg>32 handled by a guarded tail loop.

__device__ __forceinline__ float4 gather16_core(const float* __restrict__ h,
                                                int gw, int lane, int degc) {
    int c4 = lane & 3;
    int slot = lane >> 2;
    int s0 = gw << CAPSH;
    float4 acc = make_float4(0.f, 0.f, 0.f, 0.f);
    int lim = min(degc, 32);
    int si = (lane < lim) ? g_csr[s0 + lane] : 0;
    for (int jb = 0; jb < lim; jb += 16) {     // warp-uniform bound
        int j0 = jb + slot;
        int j1 = jb + 8 + slot;
        int sA = __shfl_sync(0xffffffffu, si, j0);
        int sB = __shfl_sync(0xffffffffu, si, j1);
        if (j0 < lim) {
            float4 v = *reinterpret_cast<const float4*>(h + (size_t)sA * 16 + c4 * 4);
            acc.x += v.x; acc.y += v.y; acc.z += v.z; acc.w += v.w;
        }
        if (j1 < lim) {
            float4 v = *reinterpret_cast<const float4*>(h + (size_t)sB * 16 + c4 * 4);
            acc.x += v.x; acc.y += v.y; acc.z += v.z; acc.w += v.w;
        }
    }
    if (degc > 32) {                           // rare tail (~10 nodes chip-wide)
        int lim2 = degc - 32;
        int si2 = (lane < lim2) ? g_csr[s0 + 32 + lane] : 0;
        for (int jb = 0; jb < lim2; jb += 16) {
            int j0 = jb + slot;
            int j1 = jb + 8 + slot;
            int sA = __shfl_sync(0xffffffffu, si2, j0);
            int sB = __shfl_sync(0xffffffffu, si2, j1);
            if (j0 < lim2) {
                float4 v = *reinterpret_cast<const float4*>(h + (size_t)sA * 16 + c4 * 4);
                acc.x += v.x; acc.y += v.y; acc.z += v.z; acc.w += v.w;
            }
            if (j1 < lim2) {
                float4 v = *reinterpret_cast<const float4*>(h + (size_t)sB * 16 + c4 * 4);
                acc.x += v.x; acc.y += v.y; acc.z += v.z; acc.w += v.w;
            }
        }
    }
#pragma unroll
    for (int m = 4; m < 32; m <<= 1) {
        acc.x += __shfl_xor_sync(0xffffffffu, acc.x, m);
        acc.y += __shfl_xor_sync(0xffffffffu, acc.y, m);
        acc.z += __shfl_xor_sync(0xffffffffu, acc.z, m);
        acc.w += __shfl_xor_sync(0xffffffffu, acc.w, m);
    }
    return acc;
}

// W=32: lane = (slot:2 | c4:3). Paired slots, 2 loads in flight per iteration.
__device__ __forceinline__ float4 gather32_core(const float* __restrict__ h,
                                                int gw, int lane, int degc) {
    int c4 = lane & 7;
    int slot = lane >> 3;
    int s0 = gw << CAPSH;
    float4 acc = make_float4(0.f, 0.f, 0.f, 0.f);
    int lim = min(degc, 32);
    int si = (lane < lim) ? g_csr[s0 + lane] : 0;
    for (int jb = 0; jb < lim; jb += 8) {
        int j0 = jb + slot;
        int j1 = jb + 4 + slot;
        int sA = __shfl_sync(0xffffffffu, si, j0);
        int sB = __shfl_sync(0xffffffffu, si, j1);
        if (j0 < lim) {
            float4 v = *reinterpret_cast<const float4*>(h + (size_t)sA * 32 + c4 * 4);
            acc.x += v.x; acc.y += v.y; acc.z += v.z; acc.w += v.w;
        }
        if (j1 < lim) {
            float4 v = *reinterpret_cast<const float4*>(h + (size_t)sB * 32 + c4 * 4);
            acc.x += v.x; acc.y += v.y; acc.z += v.z; acc.w += v.w;
        }
    }
    if (degc > 32) {
        int lim2 = degc - 32;
        int si2 = (lane < lim2) ? g_csr[s0 + 32 + lane] : 0;
        for (int jb = 0; jb < lim2; jb += 8) {
            int j0 = jb + slot;
            int j1 = jb + 4 + slot;
            int sA = __shfl_sync(0xffffffffu, si2, j0);
            int sB = __shfl_sync(0xffffffffu, si2, j1);
            if (j0 < lim2) {
                float4 v = *reinterpret_cast<const float4*>(h + (size_t)sA * 32 + c4 * 4);
                acc.x += v.x; acc.y += v.y; acc.z += v.z; acc.w += v.w;
            }
            if (j1 < lim2) {
                float4 v = *reinterpret_cast<const float4*>(h + (size_t)sB * 32 + c4 * 4);
                acc.x += v.x; acc.y += v.y; acc.z += v.z; acc.w += v.w;
            }
        }
    }
#pragma unroll
    for (int m = 8; m < 32; m <<= 1) {
        acc.x += __shfl_xor_sync(0xffffffffu, acc.x, m);
        acc.y += __shfl_xor_sync(0xffffffffu, acc.y, m);
        acc.z += __shfl_xor_sync(0xffffffffu, acc.z, m);
        acc.w += __shfl_xor_sync(0xffffffffu, acc.w, m);
    }
    return acc;
}

// ---------------- L0 gather (pre, W=16): bufA = relu(agg/deg + r0) ----------------

__global__ void k_g16pre() {
    int gw = (blockIdx.x * blockDim.x + threadIdx.x) >> 5;
    if (gw >= NN) return;
    int lane = threadIdx.x & 31;
    int deg = g_pos[gw];
    float4 acc = gather16_core(g_tbuf, gw, lane, min(deg, CAP));
    if (lane < 4) {
        int c4 = lane;
        float inv = 1.f / fmaxf((float)deg, 1.f);
        float4 rv = *reinterpret_cast<const float4*>(g_rbuf + (size_t)gw * 16 + c4 * 4);
        float4 o;
        o.x = fmaxf(acc.x * inv + rv.x, 0.f);
        o.y = fmaxf(acc.y * inv + rv.y, 0.f);
        o.z = fmaxf(acc.z * inv + rv.z, 0.f);
        o.w = fmaxf(acc.w * inv + rv.w, 0.f);
        *reinterpret_cast<float4*>(g_bufA + (size_t)gw * 16 + c4 * 4) = o;
    }
}

// ---------------- L1 gather-only (W=16): g_agg = sum of bufA[neighbors] ----------------

__global__ void k_g16agg() {
    int gw = (blockIdx.x * blockDim.x + threadIdx.x) >> 5;
    if (gw >= NN) return;
    int lane = threadIdx.x & 31;
    float4 acc = gather16_core(g_bufA, gw, lane, min(g_pos[gw], CAP));
    if (lane < 4)
        *reinterpret_cast<float4*>(g_agg + (size_t)gw * 16 + lane * 4) = acc;
}

// ---------------- L1 update (thread/node): bufB = relu((agg/deg)@Wl1 + b1 + bufA@Wr1) ----------------

__global__ void __launch_bounds__(128) k_update1(const float* __restrict__ Wl,
                                                 const float* __restrict__ bl,
                                                 const float* __restrict__ Wr) {
    __shared__ float sWl[16 * 32];
    __shared__ float sWr[16 * 32];
    __shared__ float sb[32];
    for (int idx = threadIdx.x; idx < 16 * 32; idx += blockDim.x) {
        sWl[idx] = Wl[idx];
        sWr[idx] = Wr[idx];
    }
    if (threadIdx.x < 32) sb[threadIdx.x] = bl[threadIdx.x];
    __syncthreads();
    int i = blockIdx.x * blockDim.x + threadIdx.x;
    if (i >= NN) return;
    float inv = 1.f / fmaxf((float)g_pos[i], 1.f);
    float acc[32];
#pragma unroll
    for (int j = 0; j < 32; j++) acc[j] = sb[j];
#pragma unroll 2
    for (int k = 0; k < 16; k++) {
        float a = g_agg[(size_t)i * 16 + k] * inv;
        float hv = g_bufA[(size_t)i * 16 + k];
#pragma unroll
        for (int j = 0; j < 32; j++)
            acc[j] += a * sWl[k * 32 + j] + hv * sWr[k * 32 + j];
    }
#pragma unroll
    for (int j = 0; j < 32; j++)
        g_bufB[(size_t)i * 32 + j] = fmaxf(acc[j], 0.f);
}

// ---------------- L2 gather-only (W=32): g_agg = sum of bufB[neighbors] ----------------

__global__ void k_g32agg() {
    int gw = (blockIdx.x * blockDim.x + threadIdx.x) >> 5;
    if (gw >= NN) return;
    int lane = threadIdx.x & 31;
    float4 acc = gather32_core(g_bufB, gw, lane, min(g_pos[gw], CAP));
    if (lane < 8)
        *reinterpret_cast<float4*>(g_agg + (size_t)gw * 32 + lane * 4) = acc;
}

// ---------------- L2 update (thread/node) + fused L3 prep + pool-zero ----------------

__global__ void __launch_bounds__(128) k_update2(const float* __restrict__ Wl,
                                                 const float* __restrict__ bl,
                                                 const float* __restrict__ Wr,
                                                 const float* __restrict__ Wl3,
                                                 const float* __restrict__ bl3,
                                                 const float* __restrict__ Wr3) {
    __shared__ float sWl[32 * 64];
    __shared__ float sWr[32 * 64];
    __shared__ float sb[64];
    __shared__ float sWl3[64 * 2];
    __shared__ float sWr3[64 * 2];
    __shared__ float sb3[2];
    for (int idx = threadIdx.x; idx < 32 * 64; idx += blockDim.x) {
        sWl[idx] = Wl[idx];
        sWr[idx] = Wr[idx];
    }
    if (threadIdx.x < 64) sb[threadIdx.x] = bl[threadIdx.x];
    if (threadIdx.x < 128) { sWl3[threadIdx.x] = Wl3[threadIdx.x]; sWr3[threadIdx.x] = Wr3[threadIdx.x]; }
    if (threadIdx.x < 2) sb3[threadIdx.x] = bl3[threadIdx.x];
    if (blockIdx.x == 0) {
        for (int idx = threadIdx.x; idx < NG * 2; idx += blockDim.x) g_pool[idx] = 0.f;
        for (int idx = threadIdx.x; idx < NG; idx += blockDim.x) g_gcnt[idx] = 0.f;
    }
    __syncthreads();
    int i = blockIdx.x * blockDim.x + threadIdx.x;
    if (i >= NN) return;
    float inv = 1.f / fmaxf((float)g_pos[i], 1.f);
    float t3p0 = 0.f, t3p1 = 0.f, r3p0 = 0.f, r3p1 = 0.f;
    for (int half = 0; half < 2; half++) {
        float acc[32];
#pragma unroll
        for (int j = 0; j < 32; j++) acc[j] = sb[half * 32 + j];
#pragma unroll 2
        for (int k = 0; k < 32; k++) {
            float a = g_agg[(size_t)i * 32 + k] * inv;
            float hv = g_bufB[(size_t)i * 32 + k];
#pragma unroll
            for (int j = 0; j < 32; j++)
                acc[j] += a * sWl[k * 64 + half * 32 + j] + hv * sWr[k * 64 + half * 32 + j];
        }
#pragma unroll
        for (int j = 0; j < 32; j++) {
            float h3 = fmaxf(acc[j], 0.f);
            int ch = half * 32 + j;
            t3p0 += h3 * sWl3[ch * 2 + 0];
            t3p1 += h3 * sWl3[ch * 2 + 1];
            r3p0 += h3 * sWr3[ch * 2 + 0];
            r3p1 += h3 * sWr3[ch * 2 + 1];
        }
    }
    reinterpret_cast<float2*>(g_tbuf)[i] = make_float2(t3p0, t3p1);
    reinterpret_cast<float2*>(g_rbuf)[i] = make_float2(r3p0 + sb3[0], r3p1 + sb3[1]);
}

// ---------------- L3 gather + pool (2 nodes/warp) + g_pos reset + last-block softmax ----------------

__global__ void __launch_bounds__(256) k_g2pool(const int* __restrict__ batch,
                                                float* __restrict__ out,
                                                int nblocks) {
    int w = (blockIdx.x * blockDim.x + threadIdx.x) >> 5;
    int lane = threadIdx.x & 31;
    int half = lane >> 4;
    int sub = lane & 15;
    int gw = w * 2 + half;
    float ax = 0.f, ay = 0.f;
    int deg = 0;
    if (gw < NN) {
        deg = g_pos[gw];
        int degc = min(deg, CAP);
        int s0 = gw << CAPSH;
        const float2* tv = reinterpret_cast<const float2*>(g_tbuf);
        for (int e = sub; e < degc; e += 16) {
            float2 v = tv[g_csr[s0 + e]];
            ax += v.x; ay += v.y;
        }
    }
#pragma unroll
    for (int m = 1; m < 16; m <<= 1) {
        ax += __shfl_xor_sync(0xffffffffu, ax, m);
        ay += __shfl_xor_sync(0xffffffffu, ay, m);
    }
    if (gw < NN && sub == 0) {
        g_pos[gw] = 0;  // reset degree counter for the next call
        float inv = 1.f / fmaxf((float)deg, 1.f);
        float2 rv = reinterpret_cast<const float2*>(g_rbuf)[gw];
        float hx = fmaxf(ax * inv + rv.x, 0.f);
        float hy = fmaxf(ay * inv + rv.y, 0.f);
        int g = batch[gw];
        atomicAdd(&g_pool[2 * g + 0], hx);
        atomicAdd(&g_pool[2 * g + 1], hy);
        atomicAdd(&g_gcnt[g], 1.f);
    }
    __shared__ int last;
    __syncthreads();
    if (threadIdx.x == 0) {
        __threadfence();
        int v = atomicAdd(&g_done, 1);
        last = (v == nblocks - 1) ? 1 : 0;
    }
    __syncthreads();
    if (last) {
        __threadfence();
        int g = threadIdx.x;
        if (g < NG) {
            float c = fmaxf(g_gcnt[g], 1.f);
            float a = g_pool[2 * g + 0] / c;
            float b = g_pool[2 * g + 1] / c;
            float m = fmaxf(a, b);
            float ea = expf(a - m);
            float eb = expf(b - m);
            float s = ea + eb;
            out[2 * g + 0] = ea / s;
            out[2 * g + 1] = eb / s;
        }
        if (threadIdx.x == 0) g_done = 0;
    }
}

extern "C" void kernel_launch(void* const* d_in, const int* in_sizes, int n_in,
                              void* d_out, int out_size) {
    const float* x = (const float*)d_in[0];
    const int* ei = (const int*)d_in[1];
    const int* batch = (const int*)d_in[2];
    const float* Wl0 = (const float*)d_in[3];
    const float* bl0 = (const float*)d_in[4];
    const float* Wr0 = (const float*)d_in[5];
    const float* Wl1 = (const float*)d_in[6];
    const float* bl1 = (const float*)d_in[7];
    const float* Wr1 = (const float*)d_in[8];
    const float* Wl2 = (const float*)d_in[9];
    const float* bl2 = (const float*)d_in[10];
    const float* Wr2 = (const float*)d_in[11];
    const float* Wl3 = (const float*)d_in[12];
    const float* bl3 = (const float*)d_in[13];
    const float* Wr3 = (const float*)d_in[14];
    float* out = (float*)d_out;

    const int* src = ei;
    const int* dst = ei + NE;

    const int TB = 256;
    auto nb = [](long n, int tb) { return (int)((n + tb - 1) / tb); };
    const int GATHER_GRID = nb((long)NN * 32, TB);       // warp per node (12500)
    const int POOL_GRID = nb((long)NN * 16, TB);         // 2 nodes per warp (6250)

    // 1. fused CSR build + L0 prep (independent halves, one launch)
    k_fillprep<<<FILL_BLOCKS + PREP_BLOCKS, TB>>>(src, dst, x, Wl0, bl0, Wr0);
    // 2. L0 gather (pre, fused elementwise epilogue)
    k_g16pre<<<GATHER_GRID, TB>>>();
    // 3. L1 gather-only
    k_g16agg<<<GATHER_GRID, TB>>>();
    // 4. L1 update (thread/node matvec)
    k_update1<<<nb(NN, 128), 128>>>(Wl1, bl1, Wr1);
    // 5. L2 gather-only
    k_g32agg<<<GATHER_GRID, TB>>>();
    // 6. L2 update + fused L3 prep + pool-zero
    k_update2<<<nb(NN, 128), 128>>>(Wl2, bl2, Wr2, Wl3, bl3, Wr3);
    // 7. L3 gather + pool + softmax
    k_g2pool<<<POOL_GRID, TB>>>(batch, out, POOL_GRID);
}